// round 2
// baseline (speedup 1.0000x reference)
#include <cuda_runtime.h>
#include <cuda_bf16.h>

// Problem constants
#define BB 8
#define LL 8192
#define DD 512
#define SF 4
#define CH 64           // number of L-chunks
#define RR (LL / CH)    // rows per chunk = 128
#define OUT_L (LL / SF) // 2048
#define D4 (DD / 4)     // float4 lanes per row = 128

// 1 MB scratch for per-chunk partial sums (later exclusive prefixes)
__device__ float g_part[BB][CH][DD];

// Phase 1: per-chunk column sums. grid (CH, BB), 128 threads (float4 per thread).
__global__ void k_partial(const float* __restrict__ x) {
    const int b = blockIdx.y;
    const int c = blockIdx.x;
    const int d4 = threadIdx.x; // 0..127
    const float4* xp = reinterpret_cast<const float4*>(
        x + ((size_t)b * LL + (size_t)c * RR) * DD) + d4;
    float4 acc = make_float4(0.f, 0.f, 0.f, 0.f);
#pragma unroll 16
    for (int r = 0; r < RR; ++r) {
        float4 v = xp[(size_t)r * D4];
        acc.x += v.x; acc.y += v.y; acc.z += v.z; acc.w += v.w;
    }
    reinterpret_cast<float4*>(g_part[b][c])[d4] = acc;
}

// Phase 2: exclusive prefix over chunks, per (b, d). grid BB, 512 threads.
__global__ void k_scan() {
    const int b = blockIdx.x;
    const int d = threadIdx.x;
    float run = 0.f;
#pragma unroll
    for (int c = 0; c < CH; ++c) {
        float t = g_part[b][c][d];
        g_part[b][c][d] = run;
        run += t;
    }
}

// Phase 3: re-scan each chunk from its exclusive base, emit every SF-th prefix mean.
// grid (CH, BB), 128 threads (float4 per thread).
__global__ void k_emit(const float* __restrict__ x, float* __restrict__ out) {
    const int b = blockIdx.y;
    const int c = blockIdx.x;
    const int d4 = threadIdx.x;
    float4 acc = reinterpret_cast<const float4*>(g_part[b][c])[d4];
    const float4* xp = reinterpret_cast<const float4*>(
        x + ((size_t)b * LL + (size_t)c * RR) * DD) + d4;
    float4* op = reinterpret_cast<float4*>(
        out + ((size_t)b * OUT_L + (size_t)c * (RR / SF)) * DD) + d4;

#pragma unroll 4
    for (int g = 0; g < RR / SF; ++g) {
#pragma unroll
        for (int s = 0; s < SF; ++s) {
            float4 v = xp[(size_t)(g * SF + s) * D4];
            acc.x += v.x; acc.y += v.y; acc.z += v.z; acc.w += v.w;
        }
        const float inv = 1.0f / (float)(c * RR + g * SF + SF);
        float4 o = make_float4(acc.x * inv, acc.y * inv, acc.z * inv, acc.w * inv);
        op[(size_t)g * D4] = o;
    }
}

extern "C" void kernel_launch(void* const* d_in, const int* in_sizes, int n_in,
                              void* d_out, int out_size) {
    const float* x = (const float*)d_in[0];
    float* out = (float*)d_out;

    dim3 grid(CH, BB);
    k_partial<<<grid, D4>>>(x);
    k_scan<<<BB, DD>>>();
    k_emit<<<grid, D4>>>(x, out);
}

// round 3
// speedup vs baseline: 1.0491x; 1.0491x over previous
#include <cuda_runtime.h>
#include <cuda_bf16.h>

// Problem constants
#define BB 8
#define LL 8192
#define DD 512
#define SF 4
#define CH 256          // number of L-chunks (quadrupled for occupancy)
#define RR (LL / CH)    // rows per chunk = 32
#define OUT_L (LL / SF) // 2048
#define D4 (DD / 4)     // float4 lanes per row = 128

// 4 MB scratch for per-chunk partial sums (later exclusive prefixes)
__device__ float g_part[BB][CH][DD];

__device__ __forceinline__ void stcs4(float4* p, float4 v) {
    asm volatile("st.global.cs.v4.f32 [%0], {%1,%2,%3,%4};"
                 :: "l"(p), "f"(v.x), "f"(v.y), "f"(v.z), "f"(v.w) : "memory");
}

// Phase 1: per-chunk column sums. grid (CH, BB), 128 threads (float4 per thread).
__global__ void k_partial(const float* __restrict__ x) {
    const int b = blockIdx.y;
    const int c = blockIdx.x;
    const int d4 = threadIdx.x; // 0..127
    const float4* xp = reinterpret_cast<const float4*>(
        x + ((size_t)b * LL + (size_t)c * RR) * DD) + d4;
    float4 acc = make_float4(0.f, 0.f, 0.f, 0.f);
#pragma unroll
    for (int r = 0; r < RR; ++r) {
        float4 v = xp[(size_t)r * D4];
        acc.x += v.x; acc.y += v.y; acc.z += v.z; acc.w += v.w;
    }
    reinterpret_cast<float4*>(g_part[b][c])[d4] = acc;
}

// Phase 2: exclusive prefix over chunks, per (b, d). grid BB, 512 threads.
__global__ void k_scan() {
    const int b = blockIdx.x;
    const int d = threadIdx.x;
    float run = 0.f;
#pragma unroll 8
    for (int c = 0; c < CH; ++c) {
        float t = g_part[b][c][d];
        g_part[b][c][d] = run;
        run += t;
    }
}

// Phase 3: re-scan each chunk from its exclusive base, emit every SF-th prefix mean.
// grid (CH, BB), 128 threads (float4 per thread). Streaming stores (evict-first)
// so output writes don't evict the L2-resident tail of x.
__global__ void k_emit(const float* __restrict__ x, float* __restrict__ out) {
    const int b = blockIdx.y;
    const int c = blockIdx.x;
    const int d4 = threadIdx.x;
    float4 acc = reinterpret_cast<const float4*>(g_part[b][c])[d4];
    const float4* xp = reinterpret_cast<const float4*>(
        x + ((size_t)b * LL + (size_t)c * RR) * DD) + d4;
    float4* op = reinterpret_cast<float4*>(
        out + ((size_t)b * OUT_L + (size_t)c * (RR / SF)) * DD) + d4;

#pragma unroll
    for (int g = 0; g < RR / SF; ++g) {
#pragma unroll
        for (int s = 0; s < SF; ++s) {
            float4 v = xp[(size_t)(g * SF + s) * D4];
            acc.x += v.x; acc.y += v.y; acc.z += v.z; acc.w += v.w;
        }
        const float inv = 1.0f / (float)(c * RR + g * SF + SF);
        float4 o = make_float4(acc.x * inv, acc.y * inv, acc.z * inv, acc.w * inv);
        stcs4(op + (size_t)g * D4, o);
    }
}

extern "C" void kernel_launch(void* const* d_in, const int* in_sizes, int n_in,
                              void* d_out, int out_size) {
    const float* x = (const float*)d_in[0];
    float* out = (float*)d_out;

    dim3 grid(CH, BB);
    k_partial<<<grid, D4>>>(x);
    k_scan<<<BB, DD>>>();
    k_emit<<<grid, D4>>>(x, out);
}